// round 11
// baseline (speedup 1.0000x reference)
#include <cuda_runtime.h>
#include <cuda_fp16.h>
#include <cstdint>

#define T_TOK 4096
#define DIM   1024
#define NE    8
#define CAP   640   // int(1.25 * 4096 / 8)

// ---------------- scratch (no cudaMalloc allowed) ----------------
__device__ int   g_topidx[T_TOK];
__device__ float g_topprob[T_TOK];
__device__ float g_probs[T_TOK * NE];
__device__ int   g_tokens[NE * CAP];
__device__ int   g_m[NE];
__device__ int   g_kept[T_TOK];

// fp16 operands
__device__ __half g_xh[T_TOK * DIM];         // 8 MB   x fp16 [t][k]
__device__ __half g_wh[NE * DIM * DIM];      // 16 MB  W fp16 [e][k][n] (native layout)

// ---------------- helpers ----------------
__device__ __forceinline__ uint32_t smem_u32(const void* p) {
    uint32_t a;
    asm("{ .reg .u64 t; cvta.to.shared.u64 t, %1; cvt.u32.u64 %0, t; }" : "=r"(a) : "l"(p));
    return a;
}
__device__ __forceinline__ void cpasync16(uint32_t dst, const void* src) {
    asm volatile("cp.async.cg.shared.global [%0], [%1], 16;"
                 :: "r"(dst), "l"(__cvta_generic_to_global(src)) : "memory");
}
__device__ __forceinline__ void cp_commit() {
    asm volatile("cp.async.commit_group;" ::: "memory");
}
__device__ __forceinline__ void cp_wait2() {
    asm volatile("cp.async.wait_group 2;" ::: "memory");
}
#define LDSM4(r0, r1, r2, r3, a)                                             \
    asm volatile("ldmatrix.sync.aligned.m8n8.x4.shared.b16 {%0,%1,%2,%3}, [%4];" \
                 : "=r"(r0), "=r"(r1), "=r"(r2), "=r"(r3) : "r"(a))
#define LDSM4T(r0, r1, r2, r3, a)                                            \
    asm volatile("ldmatrix.sync.aligned.m8n8.x4.trans.shared.b16 {%0,%1,%2,%3}, [%4];" \
                 : "=r"(r0), "=r"(r1), "=r"(r2), "=r"(r3) : "r"(a))
#define MMA16816(d, a, b0v, b1v)                                             \
    asm volatile("mma.sync.aligned.m16n8k16.row.col.f32.f16.f16.f32 "        \
                 "{%0,%1,%2,%3},{%4,%5,%6,%7},{%8,%9},{%0,%1,%2,%3};"        \
                 : "+f"((d)[0]), "+f"((d)[1]), "+f"((d)[2]), "+f"((d)[3])    \
                 : "r"((a)[0]), "r"((a)[1]), "r"((a)[2]), "r"((a)[3]),       \
                   "r"(b0v), "r"(b1v))

// ================= prep kernel =================
// blocks [0, GB)      : gating + x fp16 convert (2 tok / warp, direct Wg)
// blocks [GB, GB+WB)  : W fp32 -> fp16 streaming convert
#define PREP_GBLKS 256
#define PREP_WBLKS 1024
#define PREP_BLOCKS (PREP_GBLKS + PREP_WBLKS)

__global__ void __launch_bounds__(256) prep_kernel(
        const float* __restrict__ x,  const float* __restrict__ Wg,
        const float* __restrict__ bg, const float* __restrict__ W) {
    int bid = blockIdx.x;
    int tid = threadIdx.x;

    if (bid < PREP_GBLKS) {
        // ---- gating + x fp16 convert, 2 tokens per warp ----
        int warp = bid * 8 + (tid >> 5);
        int lane = tid & 31;
        int t0 = warp * 2, t1 = warp * 2 + 1;

        const float4* x0 = reinterpret_cast<const float4*>(x + (size_t)t0 * DIM);
        const float4* x1 = reinterpret_cast<const float4*>(x + (size_t)t1 * DIM);
        float a0[NE], a1[NE];
#pragma unroll
        for (int e = 0; e < NE; e++) { a0[e] = 0.0f; a1[e] = 0.0f; }

#pragma unroll
        for (int j = 0; j < 8; j++) {
            int d = j * 128 + lane * 4;
            float4 v0 = x0[d >> 2];
            float4 v1 = x1[d >> 2];
            float f0[4] = {v0.x, v0.y, v0.z, v0.w};
            float f1[4] = {v1.x, v1.y, v1.z, v1.w};
            __half h0[4], h1[4];
#pragma unroll
            for (int i = 0; i < 4; i++) {
                h0[i] = __float2half(f0[i]);
                h1[i] = __float2half(f1[i]);
                const float4* wg4 = reinterpret_cast<const float4*>(Wg + (size_t)(d + i) * NE);
                float4 w0 = wg4[0];
                float4 w1 = wg4[1];
                a0[0] += f0[i] * w0.x; a0[1] += f0[i] * w0.y;
                a0[2] += f0[i] * w0.z; a0[3] += f0[i] * w0.w;
                a0[4] += f0[i] * w1.x; a0[5] += f0[i] * w1.y;
                a0[6] += f0[i] * w1.z; a0[7] += f0[i] * w1.w;
                a1[0] += f1[i] * w0.x; a1[1] += f1[i] * w0.y;
                a1[2] += f1[i] * w0.z; a1[3] += f1[i] * w0.w;
                a1[4] += f1[i] * w1.x; a1[5] += f1[i] * w1.y;
                a1[6] += f1[i] * w1.z; a1[7] += f1[i] * w1.w;
            }
            *reinterpret_cast<uint2*>(g_xh + (size_t)t0 * DIM + d) = *reinterpret_cast<uint2*>(h0);
            *reinterpret_cast<uint2*>(g_xh + (size_t)t1 * DIM + d) = *reinterpret_cast<uint2*>(h1);
        }
#pragma unroll
        for (int e = 0; e < NE; e++) {
#pragma unroll
            for (int off = 16; off; off >>= 1) {
                a0[e] += __shfl_xor_sync(0xffffffffu, a0[e], off);
                a1[e] += __shfl_xor_sync(0xffffffffu, a1[e], off);
            }
        }
        if (lane == 0) {
#pragma unroll
            for (int tt = 0; tt < 2; tt++) {
                float* acc = tt ? a1 : a0;
                int t = tt ? t1 : t0;
                float l[NE], p[NE];
                float mx = -1e30f;
                int arg = 0;
#pragma unroll
                for (int e = 0; e < NE; e++) l[e] = acc[e] + bg[e];
#pragma unroll
                for (int e = 0; e < NE; e++) {
                    if (l[e] > mx) { mx = l[e]; arg = e; }
                }
                float s = 0.0f;
#pragma unroll
                for (int e = 0; e < NE; e++) { p[e] = expf(l[e] - mx); s += p[e]; }
                float inv = 1.0f / s;
#pragma unroll
                for (int e = 0; e < NE; e++) g_probs[(size_t)t * NE + e] = p[e] * inv;
                g_topidx[t]  = arg;
                g_topprob[t] = p[arg] * inv;
            }
        }
        return;
    }
    // ---- W fp32 -> fp16 streaming (8 float4 per thread) ----
    {
        int wb = bid - PREP_GBLKS;
        const float4* src = reinterpret_cast<const float4*>(W);
        uint2* dst = reinterpret_cast<uint2*>(g_wh);
        size_t u0 = (size_t)wb * 2048 + tid;
#pragma unroll
        for (int i = 0; i < 8; i++) {
            size_t u = u0 + (size_t)i * 256;
            float4 v = src[u];
            __half2 lo = __floats2half2_rn(v.x, v.y);
            __half2 hi = __floats2half2_rn(v.z, v.w);
            uint2 o;
            o.x = *reinterpret_cast<uint32_t*>(&lo);
            o.y = *reinterpret_cast<uint32_t*>(&hi);
            dst[u] = o;
        }
    }
}

// ---------------- routing scan (shfl-based) ----------------------
__global__ void __launch_bounds__(1024) route_kernel(float* __restrict__ aux_out) {
    __shared__ int   wtot[32][NE];
    __shared__ float wsum[32][NE];
    int tid  = threadIdx.x;
    int lane = tid & 31;
    int warp = tid >> 5;

    int c[NE];
#pragma unroll
    for (int e = 0; e < NE; e++) c[e] = 0;
    int myexp[4];
#pragma unroll
    for (int j = 0; j < 4; j++) {
        int t = tid * 4 + j;
        int e = g_topidx[t];
        myexp[j] = e;
        c[e]++;
    }
    int inc[NE];
#pragma unroll
    for (int e = 0; e < NE; e++) inc[e] = c[e];
#pragma unroll
    for (int off = 1; off < 32; off <<= 1) {
#pragma unroll
        for (int e = 0; e < NE; e++) {
            int v = __shfl_up_sync(0xffffffffu, inc[e], off);
            if (lane >= off) inc[e] += v;
        }
    }
    if (lane == 31) {
#pragma unroll
        for (int e = 0; e < NE; e++) wtot[warp][e] = inc[e];
    }
    __syncthreads();
    if (warp == 0) {
        int v[NE];
#pragma unroll
        for (int e = 0; e < NE; e++) v[e] = wtot[lane][e];
#pragma unroll
        for (int off = 1; off < 32; off <<= 1) {
#pragma unroll
            for (int e = 0; e < NE; e++) {
                int u = __shfl_up_sync(0xffffffffu, v[e], off);
                if (lane >= off) v[e] += u;
            }
        }
#pragma unroll
        for (int e = 0; e < NE; e++) wtot[lane][e] = v[e];
    }
    __syncthreads();

    int total[NE], run[NE];
#pragma unroll
    for (int e = 0; e < NE; e++) {
        total[e] = wtot[31][e];
        run[e]   = (warp ? wtot[warp - 1][e] : 0) + inc[e] - c[e];
    }
#pragma unroll
    for (int j = 0; j < 4; j++) {
        int t = tid * 4 + j;
        int e = myexp[j];
        run[e]++;
        int pos  = run[e];
        int keep = (pos <= CAP);
        g_kept[t] = keep;
        if (keep) g_tokens[e * CAP + pos - 1] = t;
    }
    if (tid < NE) g_m[tid] = (total[tid] < CAP) ? total[tid] : CAP;

    float s[NE];
#pragma unroll
    for (int e = 0; e < NE; e++) s[e] = 0.0f;
#pragma unroll
    for (int j = 0; j < 4; j++) {
        const float4* p4 = reinterpret_cast<const float4*>(g_probs + (size_t)(tid * 4 + j) * NE);
        float4 a = p4[0], bb = p4[1];
        s[0] += a.x; s[1] += a.y; s[2] += a.z; s[3] += a.w;
        s[4] += bb.x; s[5] += bb.y; s[6] += bb.z; s[7] += bb.w;
    }
#pragma unroll
    for (int off = 16; off; off >>= 1)
#pragma unroll
        for (int e = 0; e < NE; e++) s[e] += __shfl_xor_sync(0xffffffffu, s[e], off);
    if (lane == 0) {
#pragma unroll
        for (int e = 0; e < NE; e++) wsum[warp][e] = s[e];
    }
    __syncthreads();
    if (warp == 0) {
        float r[NE];
#pragma unroll
        for (int e = 0; e < NE; e++) r[e] = wsum[lane][e];
#pragma unroll
        for (int off = 16; off; off >>= 1)
#pragma unroll
            for (int e = 0; e < NE; e++) r[e] += __shfl_xor_sync(0xffffffffu, r[e], off);
        if (lane == 0 && aux_out != nullptr) {
            float aux = 0.0f;
            const float invT = 1.0f / (float)T_TOK;
#pragma unroll
            for (int e = 0; e < NE; e++)
                aux += ((float)total[e] * invT) * (r[e] * invT);
            *aux_out = (float)NE * aux;
        }
    }
}

// ---------------- HMMA gathered expert GEMM + dropped-row zero ---
#define GBM 128
#define GBN 128
#define GBK 32
#define NITER (DIM / GBK)          // 32
#define ATILE 8192
#define BTILE 8192
#define STAGE_BYTES (ATILE + BTILE)   // 16384
#define NSTAGE 4
#define SMEM_DATA0 1024
#define SMEM_GEMM (SMEM_DATA0 + NSTAGE * STAGE_BYTES)   // 66560
#define GRID_X (DIM / GBN)                 // 8
#define GRID_Y ((CAP + GBM - 1) / GBM)     // 5
#define NZBLK  (GRID_X * GRID_Y)           // 40

__device__ __forceinline__ uint32_t sw_a(int row, int kb) {
    return (uint32_t)(row * 64 + ((kb ^ ((row >> 1) & 3)) << 4));
}
__device__ __forceinline__ uint32_t sw_b(int k, int nc) {
    return (uint32_t)(k * 256 + ((((nc & 7) ^ (k & 7)) | (nc & 8)) << 4));
}

__global__ void __launch_bounds__(256, 2) moe_hmma_kernel(
        const float* __restrict__ bias, float* __restrict__ out) {
    int e = blockIdx.z;
    int tid  = threadIdx.x;

    if (e == NE) {
        int zb = blockIdx.y * GRID_X + blockIdx.x;   // 0..39
        float4 z = make_float4(0.f, 0.f, 0.f, 0.f);
        for (int t = zb; t < T_TOK; t += NZBLK) {
            if (!g_kept[t])
                reinterpret_cast<float4*>(out + (size_t)t * DIM)[tid] = z;
        }
        return;
    }

    int m    = g_m[e];
    int row0 = blockIdx.y * GBM;
    if (row0 >= m) return;
    int col0 = blockIdx.x * GBN;

    extern __shared__ char smem[];
    uint32_t sb = smem_u32(smem);
    int wid  = tid >> 5;
    int lane = tid & 31;
    int warp_m = wid & 3;
    int warp_n = wid >> 2;

    int*   stok  = reinterpret_cast<int*>(smem);          // [128]
    float* sprob = reinterpret_cast<float*>(smem + 512);  // [128]

    if (tid < GBM) {
        int gr  = row0 + tid;
        int tok = (gr < m) ? g_tokens[e * CAP + gr] : 0;
        stok[tid]  = tok;
        sprob[tid] = (gr < m) ? g_topprob[tok] : 0.0f;
    }
    __syncthreads();

    const __half* wbase = g_wh + (size_t)e * DIM * DIM + col0;

    int ar = tid >> 2, ak = tid & 3;
    uint32_t ad0 = sw_a(ar, ak);
    uint32_t ad1 = sw_a(ar + 64, ak);
    size_t a0row = (size_t)stok[ar] * DIM;
    size_t a1row = (size_t)stok[ar + 64] * DIM;
    int bk = tid >> 3, bn = tid & 7;
    uint32_t bd0 = sw_b(bk, bn);
    uint32_t bd1 = sw_b(bk, bn + 8);

#define ISSUE_STAGE(S, KC0)                                                   \
    do {                                                                      \
        uint32_t st = sb + SMEM_DATA0 + (uint32_t)(S) * STAGE_BYTES;          \
        cpasync16(st + ad0,         g_xh + a0row + (KC0) + ak * 8);           \
        cpasync16(st + ad1,         g_xh + a1row + (KC0) + ak * 8);           \
        const __half* wrow = wbase + (size_t)((KC0) + bk) * DIM;              \
        cpasync16(st + ATILE + bd0, wrow + bn * 8);                           \
        cpasync16(st + ATILE + bd1, wrow + bn * 8 + 64);                      \
        cp_commit();                                                          \
    } while (0)

    int q = lane >> 3, r = lane & 7;
    uint32_t a_off[2][2];
#pragma unroll
    for (int mt = 0; mt < 2; mt++)
#pragma unroll
        for (int ks = 0; ks < 2; ks++) {
            int mm = warp_m * 32 + mt * 16 + (q & 1) * 8 + r;
            int kb = ks * 2 + (q >> 1);
            a_off[mt][ks] = sw_a(mm, kb);
        }
    uint32_t b_off[4][2];
#pragma unroll
    for (int nt2 = 0; nt2 < 4; nt2++)
#pragma unroll
        for (int ks = 0; ks < 2; ks++) {
            int kk = ks * 16 + (q & 1) * 8 + r;
            int nc = warp_n * 8 + nt2 * 2 + (q >> 1);
            b_off[nt2][ks] = sw_b(kk, nc);
        }

    float acc[2][8][4];
#pragma unroll
    for (int mt = 0; mt < 2; mt++)
#pragma unroll
        for (int nt = 0; nt < 8; nt++)
#pragma unroll
            for (int j = 0; j < 4; j++) acc[mt][nt][j] = 0.0f;

    ISSUE_STAGE(0, 0);
    ISSUE_STAGE(1, GBK);
    ISSUE_STAGE(2, 2 * GBK);

    int stage = 0;
    for (int c = 0; c < NITER; c++) {
        cp_wait2();
        __syncthreads();
        if (c + 3 < NITER) {
            int s3 = stage + 3;
            if (s3 >= NSTAGE) s3 -= NSTAGE;
            ISSUE_STAGE(s3, (c + 3) * GBK);
        }

        uint32_t st = sb + SMEM_DATA0 + (uint32_t)stage * STAGE_BYTES;
#pragma unroll
        for (int ks = 0; ks < 2; ks++) {
            uint32_t ah[2][4];
#pragma unroll
            for (int mt = 0; mt < 2; mt++)
                LDSM4(ah[mt][0], ah[mt][1], ah[mt][2], ah[mt][3], st + a_off[mt][ks]);
#pragma unroll
            for (int nt2 = 0; nt2 < 4; nt2++) {
                uint32_t t0, t1, t2, t3;
                LDSM4T(t0, t1, t2, t3, st + ATILE + b_off[nt2][ks]);
#pragma unroll
                for (int mt = 0; mt < 2; mt++) {
                    MMA16816(acc[mt][nt2 * 2],     ah[mt], t0, t1);
                    MMA16816(acc[mt][nt2 * 2 + 1], ah[mt], t2, t3);
                }
            }
        }
        stage++;
        if (stage >= NSTAGE) stage -= NSTAGE;
    }

    int tq = lane >> 2;
    int tr = lane & 3;
    const float* be = bias + (size_t)e * DIM;
#pragma unroll
    for (int nt = 0; nt < 8; nt++) {
        int col = col0 + warp_n * 64 + nt * 8 + tr * 2;
        float2 bb = *reinterpret_cast<const float2*>(be + col);
#pragma unroll
        for (int mt = 0; mt < 2; mt++) {
#pragma unroll
            for (int h = 0; h < 2; h++) {
                int rw = warp_m * 32 + mt * 16 + h * 8 + tq;
                int gr = row0 + rw;
                if (gr < m) {
                    int   tok = stok[rw];
                    float p   = sprob[rw];
                    float2 o;
                    o.x = (acc[mt][nt][h * 2 + 0] + bb.x) * p;
                    o.y = (acc[mt][nt][h * 2 + 1] + bb.y) * p;
                    *reinterpret_cast<float2*>(out + (size_t)tok * DIM + col) = o;
                }
            }
        }
    }
}

// ---------------- launch ----------------
extern "C" void kernel_launch(void* const* d_in, const int* in_sizes, int n_in,
                              void* d_out, int out_size) {
    const float* x  = (const float*)d_in[0];   // [T, D]
    const float* Wg = (const float*)d_in[1];   // [D, E]
    const float* bg = (const float*)d_in[2];   // [E]
    const float* W  = (const float*)d_in[3];   // [E, D, D]
    const float* b  = (const float*)d_in[4];   // [E, D]
    float* out = (float*)d_out;

    // prep: gating/x-convert (direct Wg, 2tok/warp) + W fp16 stream-convert
    prep_kernel<<<PREP_BLOCKS, 256>>>(x, Wg, bg, W);

    // routing scan + aux loss (+ kept flags)
    float* aux_out = (out_size > T_TOK * DIM) ? (out + (size_t)T_TOK * DIM) : nullptr;
    route_kernel<<<1, 1024>>>(aux_out);

    // HMMA gathered expert GEMM + dropped-row zeroing in one grid
    cudaFuncSetAttribute(moe_hmma_kernel,
                         cudaFuncAttributeMaxDynamicSharedMemorySize, SMEM_GEMM);
    dim3 grid(GRID_X, GRID_Y, NE + 1);
    moe_hmma_kernel<<<grid, 256, SMEM_GEMM>>>(b, out);
}

// round 14
// speedup vs baseline: 1.6719x; 1.6719x over previous
#include <cuda_runtime.h>
#include <cuda_fp16.h>
#include <cstdint>

#define T_TOK 4096
#define DIM   1024
#define NE    8
#define CAP   640   // int(1.25 * 4096 / 8)

// ---------------- scratch (no cudaMalloc allowed) ----------------
__device__ int   g_topidx[T_TOK];
__device__ float g_topprob[T_TOK];
__device__ float g_probs[T_TOK * NE];
__device__ int   g_tokens[NE * CAP];
__device__ int   g_m[NE];

// fp16 operands
__device__ __half g_xh[T_TOK * DIM];         // 8 MB   x fp16 [t][k]
__device__ __half g_wh[NE * DIM * DIM];      // 16 MB  W fp16 [e][k][n] (native layout)

// ---------------- helpers ----------------
__device__ __forceinline__ uint32_t smem_u32(const void* p) {
    uint32_t a;
    asm("{ .reg .u64 t; cvta.to.shared.u64 t, %1; cvt.u32.u64 %0, t; }" : "=r"(a) : "l"(p));
    return a;
}
__device__ __forceinline__ void cpasync16(uint32_t dst, const void* src) {
    asm volatile("cp.async.cg.shared.global [%0], [%1], 16;"
                 :: "r"(dst), "l"(__cvta_generic_to_global(src)) : "memory");
}
__device__ __forceinline__ void cp_commit() {
    asm volatile("cp.async.commit_group;" ::: "memory");
}
__device__ __forceinline__ void cp_wait2() {
    asm volatile("cp.async.wait_group 2;" ::: "memory");
}
#define LDSM4(r0, r1, r2, r3, a)                                             \
    asm volatile("ldmatrix.sync.aligned.m8n8.x4.shared.b16 {%0,%1,%2,%3}, [%4];" \
                 : "=r"(r0), "=r"(r1), "=r"(r2), "=r"(r3) : "r"(a))
#define LDSM4T(r0, r1, r2, r3, a)                                            \
    asm volatile("ldmatrix.sync.aligned.m8n8.x4.trans.shared.b16 {%0,%1,%2,%3}, [%4];" \
                 : "=r"(r0), "=r"(r1), "=r"(r2), "=r"(r3) : "r"(a))
#define MMA16816(d, a, b0v, b1v)                                             \
    asm volatile("mma.sync.aligned.m16n8k16.row.col.f32.f16.f16.f32 "        \
                 "{%0,%1,%2,%3},{%4,%5,%6,%7},{%8,%9},{%0,%1,%2,%3};"        \
                 : "+f"((d)[0]), "+f"((d)[1]), "+f"((d)[2]), "+f"((d)[3])    \
                 : "r"((a)[0]), "r"((a)[1]), "r"((a)[2]), "r"((a)[3]),       \
                   "r"(b0v), "r"(b1v))

// ================= prep kernel =================
// blocks [0, GB)            : gating + x fp16 convert (2 tok / warp)
// blocks [GB, GB+WB)        : W fp32 -> fp16 streaming convert (no transpose)
// blocks [GB+WB, GB+WB+ZB)  : zero out[16MB]
#define PREP_GBLKS 256
#define PREP_WBLKS 1024
#define PREP_ZBLKS 512
#define PREP_BLOCKS (PREP_GBLKS + PREP_WBLKS + PREP_ZBLKS)

__global__ void __launch_bounds__(256) prep_kernel(
        const float* __restrict__ x,  const float* __restrict__ Wg,
        const float* __restrict__ bg, const float* __restrict__ W,
        float* __restrict__ out) {
    int bid = blockIdx.x;
    int tid = threadIdx.x;

    if (bid < PREP_GBLKS) {
        // ---- gating + x fp16 convert ----
        int warp = bid * 8 + (tid >> 5);
        int lane = tid & 31;
        int t0 = warp * 2, t1 = warp * 2 + 1;

        const float4* x0 = reinterpret_cast<const float4*>(x + (size_t)t0 * DIM);
        const float4* x1 = reinterpret_cast<const float4*>(x + (size_t)t1 * DIM);
        float a0[NE], a1[NE];
#pragma unroll
        for (int e = 0; e < NE; e++) { a0[e] = 0.0f; a1[e] = 0.0f; }

#pragma unroll
        for (int j = 0; j < 8; j++) {
            int d = j * 128 + lane * 4;
            float4 v0 = x0[d >> 2];
            float4 v1 = x1[d >> 2];
            float f0[4] = {v0.x, v0.y, v0.z, v0.w};
            float f1[4] = {v1.x, v1.y, v1.z, v1.w};
            __half h0[4], h1[4];
#pragma unroll
            for (int i = 0; i < 4; i++) {
                h0[i] = __float2half(f0[i]);
                h1[i] = __float2half(f1[i]);
                const float4* wg4 = reinterpret_cast<const float4*>(Wg + (size_t)(d + i) * NE);
                float4 w0 = wg4[0];
                float4 w1 = wg4[1];
                a0[0] += f0[i] * w0.x; a0[1] += f0[i] * w0.y;
                a0[2] += f0[i] * w0.z; a0[3] += f0[i] * w0.w;
                a0[4] += f0[i] * w1.x; a0[5] += f0[i] * w1.y;
                a0[6] += f0[i] * w1.z; a0[7] += f0[i] * w1.w;
                a1[0] += f1[i] * w0.x; a1[1] += f1[i] * w0.y;
                a1[2] += f1[i] * w0.z; a1[3] += f1[i] * w0.w;
                a1[4] += f1[i] * w1.x; a1[5] += f1[i] * w1.y;
                a1[6] += f1[i] * w1.z; a1[7] += f1[i] * w1.w;
            }
            *reinterpret_cast<uint2*>(g_xh + (size_t)t0 * DIM + d) = *reinterpret_cast<uint2*>(h0);
            *reinterpret_cast<uint2*>(g_xh + (size_t)t1 * DIM + d) = *reinterpret_cast<uint2*>(h1);
        }
#pragma unroll
        for (int e = 0; e < NE; e++) {
#pragma unroll
            for (int off = 16; off; off >>= 1) {
                a0[e] += __shfl_xor_sync(0xffffffffu, a0[e], off);
                a1[e] += __shfl_xor_sync(0xffffffffu, a1[e], off);
            }
        }
        if (lane == 0) {
#pragma unroll
            for (int tt = 0; tt < 2; tt++) {
                float* acc = tt ? a1 : a0;
                int t = tt ? t1 : t0;
                float l[NE], p[NE];
                float mx = -1e30f;
                int arg = 0;
#pragma unroll
                for (int e = 0; e < NE; e++) l[e] = acc[e] + bg[e];
#pragma unroll
                for (int e = 0; e < NE; e++) {
                    if (l[e] > mx) { mx = l[e]; arg = e; }
                }
                float s = 0.0f;
#pragma unroll
                for (int e = 0; e < NE; e++) { p[e] = expf(l[e] - mx); s += p[e]; }
                float inv = 1.0f / s;
#pragma unroll
                for (int e = 0; e < NE; e++) g_probs[(size_t)t * NE + e] = p[e] * inv;
                g_topidx[t]  = arg;
                g_topprob[t] = p[arg] * inv;
            }
        }
        return;
    }
    if (bid < PREP_GBLKS + PREP_WBLKS) {
        // ---- W fp32 -> fp16 streaming (8 float4 per thread) ----
        int wb = bid - PREP_GBLKS;
        const float4* src = reinterpret_cast<const float4*>(W);
        uint2* dst = reinterpret_cast<uint2*>(g_wh);
        size_t u0 = (size_t)wb * 2048 + tid;
#pragma unroll
        for (int i = 0; i < 8; i++) {
            size_t u = u0 + (size_t)i * 256;
            float4 v = src[u];
            __half2 lo = __floats2half2_rn(v.x, v.y);
            __half2 hi = __floats2half2_rn(v.z, v.w);
            uint2 o;
            o.x = *reinterpret_cast<uint32_t*>(&lo);
            o.y = *reinterpret_cast<uint32_t*>(&hi);
            dst[u] = o;
        }
        return;
    }
    // ---- zero out (full 16 MB, 8 float4 per thread) ----
    {
        int zb = bid - PREP_GBLKS - PREP_WBLKS;
        float4 z = make_float4(0.f, 0.f, 0.f, 0.f);
        float4* o4 = reinterpret_cast<float4*>(out) + (size_t)zb * 2048 + tid;
#pragma unroll
        for (int j = 0; j < 8; j++) o4[j * 256] = z;
    }
}

// ---------------- routing scan (shfl-based) ----------------------
__global__ void __launch_bounds__(1024) route_kernel(float* __restrict__ aux_out) {
    __shared__ int   wtot[32][NE];
    __shared__ float wsum[32][NE];
    int tid  = threadIdx.x;
    int lane = tid & 31;
    int warp = tid >> 5;

    int c[NE];
#pragma unroll
    for (int e = 0; e < NE; e++) c[e] = 0;
    int myexp[4];
#pragma unroll
    for (int j = 0; j < 4; j++) {
        int t = tid * 4 + j;
        int e = g_topidx[t];
        myexp[j] = e;
        c[e]++;
    }
    int inc[NE];
#pragma unroll
    for (int e = 0; e < NE; e++) inc[e] = c[e];
#pragma unroll
    for (int off = 1; off < 32; off <<= 1) {
#pragma unroll
        for (int e = 0; e < NE; e++) {
            int v = __shfl_up_sync(0xffffffffu, inc[e], off);
            if (lane >= off) inc[e] += v;
        }
    }
    if (lane == 31) {
#pragma unroll
        for (int e = 0; e < NE; e++) wtot[warp][e] = inc[e];
    }
    __syncthreads();
    if (warp == 0) {
        int v[NE];
#pragma unroll
        for (int e = 0; e < NE; e++) v[e] = wtot[lane][e];
#pragma unroll
        for (int off = 1; off < 32; off <<= 1) {
#pragma unroll
            for (int e = 0; e < NE; e++) {
                int u = __shfl_up_sync(0xffffffffu, v[e], off);
                if (lane >= off) v[e] += u;
            }
        }
#pragma unroll
        for (int e = 0; e < NE; e++) wtot[lane][e] = v[e];
    }
    __syncthreads();

    int total[NE], run[NE];
#pragma unroll
    for (int e = 0; e < NE; e++) {
        total[e] = wtot[31][e];
        run[e]   = (warp ? wtot[warp - 1][e] : 0) + inc[e] - c[e];
    }
#pragma unroll
    for (int j = 0; j < 4; j++) {
        int t = tid * 4 + j;
        int e = myexp[j];
        run[e]++;
        int pos = run[e];
        if (pos <= CAP) g_tokens[e * CAP + pos - 1] = t;
    }
    if (tid < NE) g_m[tid] = (total[tid] < CAP) ? total[tid] : CAP;

    float s[NE];
#pragma unroll
    for (int e = 0; e < NE; e++) s[e] = 0.0f;
#pragma unroll
    for (int j = 0; j < 4; j++) {
        const float4* p4 = reinterpret_cast<const float4*>(g_probs + (size_t)(tid * 4 + j) * NE);
        float4 a = p4[0], bb = p4[1];
        s[0] += a.x; s[1] += a.y; s[2] += a.z; s[3] += a.w;
        s[4] += bb.x; s[5] += bb.y; s[6] += bb.z; s[7] += bb.w;
    }
#pragma unroll
    for (int off = 16; off; off >>= 1)
#pragma unroll
        for (int e = 0; e < NE; e++) s[e] += __shfl_xor_sync(0xffffffffu, s[e], off);
    if (lane == 0) {
#pragma unroll
        for (int e = 0; e < NE; e++) wsum[warp][e] = s[e];
    }
    __syncthreads();
    if (warp == 0) {
        float r[NE];
#pragma unroll
        for (int e = 0; e < NE; e++) r[e] = wsum[lane][e];
#pragma unroll
        for (int off = 16; off; off >>= 1)
#pragma unroll
            for (int e = 0; e < NE; e++) r[e] += __shfl_xor_sync(0xffffffffu, r[e], off);
        if (lane == 0 && aux_out != nullptr) {
            float aux = 0.0f;
            const float invT = 1.0f / (float)T_TOK;
#pragma unroll
            for (int e = 0; e < NE; e++)
                aux += ((float)total[e] * invT) * (r[e] * invT);
            *aux_out = (float)NE * aux;
        }
    }
}

// ---------------- HMMA gathered expert GEMM ----------------------
// block 128x128x32, 8 warps (4 M x 2 N), warp tile 32x64, 4-stage pipe.
// A: gathered x rows [m][k] (64B rows, XOR swizzle), plain ldmatrix.
// B: W native [k][n] tile (256B rows, chunk-XOR swizzle), ldmatrix.trans.
#define GBM 128
#define GBN 128
#define GBK 32
#define NITER (DIM / GBK)          // 32
#define ATILE 8192                 // 128 rows x 32 fp16
#define BTILE 8192                 // 32 rows x 128 fp16
#define STAGE_BYTES (ATILE + BTILE)   // 16384
#define NSTAGE 4
#define SMEM_DATA0 1024
#define SMEM_GEMM (SMEM_DATA0 + NSTAGE * STAGE_BYTES)   // 66560

// A tile: row-major [m][32], 64B/row; chunk xor (row>>1)&3
__device__ __forceinline__ uint32_t sw_a(int row, int kb) {
    return (uint32_t)(row * 64 + ((kb ^ ((row >> 1) & 3)) << 4));
}
// B tile: row-major [k][128], 256B/row; 16B-chunk nc xor (k&7) on low 3 bits
__device__ __forceinline__ uint32_t sw_b(int k, int nc) {
    return (uint32_t)(k * 256 + ((((nc & 7) ^ (k & 7)) | (nc & 8)) << 4));
}

__global__ void __launch_bounds__(256, 2) moe_hmma_kernel(
        const float* __restrict__ bias, float* __restrict__ out) {
    int e    = blockIdx.z;
    int m    = g_m[e];
    int row0 = blockIdx.y * GBM;
    if (row0 >= m) return;
    int col0 = blockIdx.x * GBN;

    extern __shared__ char smem[];
    uint32_t sb = smem_u32(smem);
    int tid  = threadIdx.x;
    int wid  = tid >> 5;
    int lane = tid & 31;
    int warp_m = wid & 3;       // m offset *32
    int warp_n = wid >> 2;      // n offset *64

    int*   stok  = reinterpret_cast<int*>(smem);          // [128]
    float* sprob = reinterpret_cast<float*>(smem + 512);  // [128]

    if (tid < GBM) {
        int gr  = row0 + tid;
        int tok = (gr < m) ? g_tokens[e * CAP + gr] : 0;
        stok[tid]  = tok;
        sprob[tid] = (gr < m) ? g_topprob[tok] : 0.0f;
    }
    __syncthreads();

    const __half* wbase = g_wh + (size_t)e * DIM * DIM + col0;   // [k][n] slab

    // A loader: rows tid/4 and tid/4+64, k-chunk tid%4
    int ar = tid >> 2, ak = tid & 3;
    uint32_t ad0 = sw_a(ar, ak);
    uint32_t ad1 = sw_a(ar + 64, ak);
    size_t a0row = (size_t)stok[ar] * DIM;
    size_t a1row = (size_t)stok[ar + 64] * DIM;
    // B loader: k-row tid/8, chunks tid%8 and 8+(tid%8)
    int bk = tid >> 3, bn = tid & 7;
    uint32_t bd0 = sw_b(bk, bn);
    uint32_t bd1 = sw_b(bk, bn + 8);

#define ISSUE_STAGE(S, KC0)                                                   \
    do {                                                                      \
        uint32_t st = sb + SMEM_DATA0 + (uint32_t)(S) * STAGE_BYTES;          \
        cpasync16(st + ad0,         g_xh + a0row + (KC0) + ak * 8);           \
        cpasync16(st + ad1,         g_xh + a1row + (KC0) + ak * 8);           \
        const __half* wrow = wbase + (size_t)((KC0) + bk) * DIM;              \
        cpasync16(st + ATILE + bd0, wrow + bn * 8);                           \
        cpasync16(st + ATILE + bd1, wrow + bn * 8 + 64);                      \
        cp_commit();                                                          \
    } while (0)

    // A ldmatrix lane offsets (plain, x4: m16 x k16)
    int q = lane >> 3, r = lane & 7;
    uint32_t a_off[2][2];
#pragma unroll
    for (int mt = 0; mt < 2; mt++)
#pragma unroll
        for (int ks = 0; ks < 2; ks++) {
            int mm = warp_m * 32 + mt * 16 + (q & 1) * 8 + r;
            int kb = ks * 2 + (q >> 1);
            a_off[mt][ks] = sw_a(mm, kb);
        }
    // B ldmatrix.trans lane offsets
    uint32_t b_off[4][2];
#pragma unroll
    for (int nt2 = 0; nt2 < 4; nt2++)
#pragma unroll
        for (int ks = 0; ks < 2; ks++) {
            int kk = ks * 16 + (q & 1) * 8 + r;          // k row
            int nc = warp_n * 8 + nt2 * 2 + (q >> 1);    // 16B chunk along n
            b_off[nt2][ks] = sw_b(kk, nc);
        }

    float acc[2][8][4];
#pragma unroll
    for (int mt = 0; mt < 2; mt++)
#pragma unroll
        for (int nt = 0; nt < 8; nt++)
#pragma unroll
            for (int j = 0; j < 4; j++) acc[mt][nt][j] = 0.0f;

    ISSUE_STAGE(0, 0);
    ISSUE_STAGE(1, GBK);
    ISSUE_STAGE(2, 2 * GBK);

    int stage = 0;
    for (int c = 0; c < NITER; c++) {
        cp_wait2();
        __syncthreads();
        if (c + 3 < NITER) {
            int s3 = stage + 3;
            if (s3 >= NSTAGE) s3 -= NSTAGE;
            ISSUE_STAGE(s3, (c + 3) * GBK);
        }

        uint32_t st = sb + SMEM_DATA0 + (uint32_t)stage * STAGE_BYTES;
#pragma unroll
        for (int ks = 0; ks < 2; ks++) {
            uint32_t ah[2][4];
#pragma unroll
            for (int mt = 0; mt < 2; mt++)
                LDSM4(ah[mt][0], ah[mt][1], ah[mt][2], ah[mt][3], st + a_off[mt][ks]);
#pragma unroll
            for (int nt2 = 0; nt2 < 4; nt2++) {
                uint32_t t0, t1, t2, t3;
                LDSM4T(t0, t1, t2, t3, st + ATILE + b_off[nt2][ks]);
#pragma unroll
                for (int mt = 0; mt < 2; mt++) {
                    MMA16816(acc[mt][nt2 * 2],     ah[mt], t0, t1);
                    MMA16816(acc[mt][nt2 * 2 + 1], ah[mt], t2, t3);
                }
            }
        }
        stage++;
        if (stage >= NSTAGE) stage -= NSTAGE;
    }

    int tq = lane >> 2;
    int tr = lane & 3;
    const float* be = bias + (size_t)e * DIM;
#pragma unroll
    for (int nt = 0; nt < 8; nt++) {
        int col = col0 + warp_n * 64 + nt * 8 + tr * 2;
        float2 bb = *reinterpret_cast<const float2*>(be + col);
#pragma unroll
        for (int mt = 0; mt < 2; mt++) {
#pragma unroll
            for (int h = 0; h < 2; h++) {
                int rw = warp_m * 32 + mt * 16 + h * 8 + tq;
                int gr = row0 + rw;
                if (gr < m) {
                    int   tok = stok[rw];
                    float p   = sprob[rw];
                    float2 o;
                    o.x = (acc[mt][nt][h * 2 + 0] + bb.x) * p;
                    o.y = (acc[mt][nt][h * 2 + 1] + bb.y) * p;
                    *reinterpret_cast<float2*>(out + (size_t)tok * DIM + col) = o;
                }
            }
        }
    }
}

// ---------------- launch ----------------
extern "C" void kernel_launch(void* const* d_in, const int* in_sizes, int n_in,
                              void* d_out, int out_size) {
    const float* x  = (const float*)d_in[0];   // [T, D]
    const float* Wg = (const float*)d_in[1];   // [D, E]
    const float* bg = (const float*)d_in[2];   // [E]
    const float* W  = (const float*)d_in[3];   // [E, D, D]
    const float* b  = (const float*)d_in[4];   // [E, D]
    float* out = (float*)d_out;

    // fused prep: gating/x-convert + W fp16 stream-convert + zero(out)
    prep_kernel<<<PREP_BLOCKS, 256>>>(x, Wg, bg, W, out);

    // routing scan + aux loss
    float* aux_out = (out_size > T_TOK * DIM) ? (out + (size_t)T_TOK * DIM) : nullptr;
    route_kernel<<<1, 1024>>>(aux_out);

    // HMMA gathered expert GEMM (single-pass fp16, trans-B)
    cudaFuncSetAttribute(moe_hmma_kernel,
                         cudaFuncAttributeMaxDynamicSharedMemorySize, SMEM_GEMM);
    dim3 grid(DIM / GBN, (CAP + GBM - 1) / GBM, NE);
    moe_hmma_kernel<<<grid, 256, SMEM_GEMM>>>(b, out);
}

// round 17
// speedup vs baseline: 1.7044x; 1.0194x over previous
#include <cuda_runtime.h>
#include <cuda_fp16.h>
#include <cstdint>

#define T_TOK 4096
#define DIM   1024
#define NE    8
#define CAP   640   // int(1.25 * 4096 / 8)

// ---------------- scratch (no cudaMalloc allowed) ----------------
__device__ int   g_topidx[T_TOK];
__device__ float g_topprob[T_TOK];
__device__ float g_probs[T_TOK * NE];
__device__ int   g_tokens[NE * CAP];
__device__ int   g_m[NE];

// fp16 operands
__device__ __half g_xh[T_TOK * DIM];         // 8 MB   x fp16 [t][k]
__device__ __half g_wh[NE * DIM * DIM];      // 16 MB  W fp16 [e][k][n] (native layout)

// ---------------- helpers ----------------
__device__ __forceinline__ uint32_t smem_u32(const void* p) {
    uint32_t a;
    asm("{ .reg .u64 t; cvta.to.shared.u64 t, %1; cvt.u32.u64 %0, t; }" : "=r"(a) : "l"(p));
    return a;
}
__device__ __forceinline__ void cpasync16(uint32_t dst, const void* src) {
    asm volatile("cp.async.cg.shared.global [%0], [%1], 16;"
                 :: "r"(dst), "l"(__cvta_generic_to_global(src)) : "memory");
}
__device__ __forceinline__ void cp_commit() {
    asm volatile("cp.async.commit_group;" ::: "memory");
}
__device__ __forceinline__ void cp_wait2() {
    asm volatile("cp.async.wait_group 2;" ::: "memory");
}
#define LDSM4(r0, r1, r2, r3, a)                                             \
    asm volatile("ldmatrix.sync.aligned.m8n8.x4.shared.b16 {%0,%1,%2,%3}, [%4];" \
                 : "=r"(r0), "=r"(r1), "=r"(r2), "=r"(r3) : "r"(a))
#define LDSM4T(r0, r1, r2, r3, a)                                            \
    asm volatile("ldmatrix.sync.aligned.m8n8.x4.trans.shared.b16 {%0,%1,%2,%3}, [%4];" \
                 : "=r"(r0), "=r"(r1), "=r"(r2), "=r"(r3) : "r"(a))
#define MMA16816(d, a, b0v, b1v)                                             \
    asm volatile("mma.sync.aligned.m16n8k16.row.col.f32.f16.f16.f32 "        \
                 "{%0,%1,%2,%3},{%4,%5,%6,%7},{%8,%9},{%0,%1,%2,%3};"        \
                 : "+f"((d)[0]), "+f"((d)[1]), "+f"((d)[2]), "+f"((d)[3])    \
                 : "r"((a)[0]), "r"((a)[1]), "r"((a)[2]), "r"((a)[3]),       \
                   "r"(b0v), "r"(b1v))

// ================= streaming kernel: W convert + zero out =========
// blocks [0, WB)      : W fp32 -> fp16 streaming convert
// blocks [WB, WB+ZB)  : zero out[16MB]
#define WZ_WBLKS 1024
#define WZ_ZBLKS 512
#define WZ_BLOCKS (WZ_WBLKS + WZ_ZBLKS)

__global__ void __launch_bounds__(256) wconv_zero_kernel(
        const float* __restrict__ W, float* __restrict__ out) {
    int bid = blockIdx.x;
    int tid = threadIdx.x;

    if (bid < WZ_WBLKS) {
        const float4* src = reinterpret_cast<const float4*>(W);
        uint2* dst = reinterpret_cast<uint2*>(g_wh);
        size_t u0 = (size_t)bid * 2048 + tid;
#pragma unroll
        for (int i = 0; i < 8; i++) {
            size_t u = u0 + (size_t)i * 256;
            float4 v = src[u];
            __half2 lo = __floats2half2_rn(v.x, v.y);
            __half2 hi = __floats2half2_rn(v.z, v.w);
            uint2 o;
            o.x = *reinterpret_cast<uint32_t*>(&lo);
            o.y = *reinterpret_cast<uint32_t*>(&hi);
            dst[u] = o;
        }
        return;
    }
    {
        int zb = bid - WZ_WBLKS;
        float4 z = make_float4(0.f, 0.f, 0.f, 0.f);
        float4* o4 = reinterpret_cast<float4*>(out) + (size_t)zb * 2048 + tid;
#pragma unroll
        for (int j = 0; j < 8; j++) o4[j * 256] = z;
    }
}

// ================= gating kernel (2 tok / warp) ===================
__global__ void __launch_bounds__(256) gating_kernel(
        const float* __restrict__ x,  const float* __restrict__ Wg,
        const float* __restrict__ bg) {
    int bid = blockIdx.x;
    int tid = threadIdx.x;
    int warp = bid * 8 + (tid >> 5);
    int lane = tid & 31;
    int t0 = warp * 2, t1 = warp * 2 + 1;

    const float4* x0 = reinterpret_cast<const float4*>(x + (size_t)t0 * DIM);
    const float4* x1 = reinterpret_cast<const float4*>(x + (size_t)t1 * DIM);
    float a0[NE], a1[NE];
#pragma unroll
    for (int e = 0; e < NE; e++) { a0[e] = 0.0f; a1[e] = 0.0f; }

#pragma unroll
    for (int j = 0; j < 8; j++) {
        int d = j * 128 + lane * 4;
        float4 v0 = x0[d >> 2];
        float4 v1 = x1[d >> 2];
        float f0[4] = {v0.x, v0.y, v0.z, v0.w};
        float f1[4] = {v1.x, v1.y, v1.z, v1.w};
        __half h0[4], h1[4];
#pragma unroll
        for (int i = 0; i < 4; i++) {
            h0[i] = __float2half(f0[i]);
            h1[i] = __float2half(f1[i]);
            const float4* wg4 = reinterpret_cast<const float4*>(Wg + (size_t)(d + i) * NE);
            float4 w0 = wg4[0];
            float4 w1 = wg4[1];
            a0[0] += f0[i] * w0.x; a0[1] += f0[i] * w0.y;
            a0[2] += f0[i] * w0.z; a0[3] += f0[i] * w0.w;
            a0[4] += f0[i] * w1.x; a0[5] += f0[i] * w1.y;
            a0[6] += f0[i] * w1.z; a0[7] += f0[i] * w1.w;
            a1[0] += f1[i] * w0.x; a1[1] += f1[i] * w0.y;
            a1[2] += f1[i] * w0.z; a1[3] += f1[i] * w0.w;
            a1[4] += f1[i] * w1.x; a1[5] += f1[i] * w1.y;
            a1[6] += f1[i] * w1.z; a1[7] += f1[i] * w1.w;
        }
        *reinterpret_cast<uint2*>(g_xh + (size_t)t0 * DIM + d) = *reinterpret_cast<uint2*>(h0);
        *reinterpret_cast<uint2*>(g_xh + (size_t)t1 * DIM + d) = *reinterpret_cast<uint2*>(h1);
    }
#pragma unroll
    for (int e = 0; e < NE; e++) {
#pragma unroll
        for (int off = 16; off; off >>= 1) {
            a0[e] += __shfl_xor_sync(0xffffffffu, a0[e], off);
            a1[e] += __shfl_xor_sync(0xffffffffu, a1[e], off);
        }
    }
    if (lane == 0) {
#pragma unroll
        for (int tt = 0; tt < 2; tt++) {
            float* acc = tt ? a1 : a0;
            int t = tt ? t1 : t0;
            float l[NE], p[NE];
            float mx = -1e30f;
            int arg = 0;
#pragma unroll
            for (int e = 0; e < NE; e++) l[e] = acc[e] + bg[e];
#pragma unroll
            for (int e = 0; e < NE; e++) {
                if (l[e] > mx) { mx = l[e]; arg = e; }
            }
            float s = 0.0f;
#pragma unroll
            for (int e = 0; e < NE; e++) { p[e] = expf(l[e] - mx); s += p[e]; }
            float inv = 1.0f / s;
#pragma unroll
            for (int e = 0; e < NE; e++) g_probs[(size_t)t * NE + e] = p[e] * inv;
            g_topidx[t]  = arg;
            g_topprob[t] = p[arg] * inv;
        }
    }
}

// ---------------- routing scan (shfl-based) ----------------------
__global__ void __launch_bounds__(1024) route_kernel(float* __restrict__ aux_out) {
    __shared__ int   wtot[32][NE];
    __shared__ float wsum[32][NE];
    int tid  = threadIdx.x;
    int lane = tid & 31;
    int warp = tid >> 5;

    int c[NE];
#pragma unroll
    for (int e = 0; e < NE; e++) c[e] = 0;
    int myexp[4];
#pragma unroll
    for (int j = 0; j < 4; j++) {
        int t = tid * 4 + j;
        int e = g_topidx[t];
        myexp[j] = e;
        c[e]++;
    }
    int inc[NE];
#pragma unroll
    for (int e = 0; e < NE; e++) inc[e] = c[e];
#pragma unroll
    for (int off = 1; off < 32; off <<= 1) {
#pragma unroll
        for (int e = 0; e < NE; e++) {
            int v = __shfl_up_sync(0xffffffffu, inc[e], off);
            if (lane >= off) inc[e] += v;
        }
    }
    if (lane == 31) {
#pragma unroll
        for (int e = 0; e < NE; e++) wtot[warp][e] = inc[e];
    }
    __syncthreads();
    if (warp == 0) {
        int v[NE];
#pragma unroll
        for (int e = 0; e < NE; e++) v[e] = wtot[lane][e];
#pragma unroll
        for (int off = 1; off < 32; off <<= 1) {
#pragma unroll
            for (int e = 0; e < NE; e++) {
                int u = __shfl_up_sync(0xffffffffu, v[e], off);
                if (lane >= off) v[e] += u;
            }
        }
#pragma unroll
        for (int e = 0; e < NE; e++) wtot[lane][e] = v[e];
    }
    __syncthreads();

    int total[NE], run[NE];
#pragma unroll
    for (int e = 0; e < NE; e++) {
        total[e] = wtot[31][e];
        run[e]   = (warp ? wtot[warp - 1][e] : 0) + inc[e] - c[e];
    }
#pragma unroll
    for (int j = 0; j < 4; j++) {
        int t = tid * 4 + j;
        int e = myexp[j];
        run[e]++;
        int pos = run[e];
        if (pos <= CAP) g_tokens[e * CAP + pos - 1] = t;
    }
    if (tid < NE) g_m[tid] = (total[tid] < CAP) ? total[tid] : CAP;

    float s[NE];
#pragma unroll
    for (int e = 0; e < NE; e++) s[e] = 0.0f;
#pragma unroll
    for (int j = 0; j < 4; j++) {
        const float4* p4 = reinterpret_cast<const float4*>(g_probs + (size_t)(tid * 4 + j) * NE);
        float4 a = p4[0], bb = p4[1];
        s[0] += a.x; s[1] += a.y; s[2] += a.z; s[3] += a.w;
        s[4] += bb.x; s[5] += bb.y; s[6] += bb.z; s[7] += bb.w;
    }
#pragma unroll
    for (int off = 16; off; off >>= 1)
#pragma unroll
        for (int e = 0; e < NE; e++) s[e] += __shfl_xor_sync(0xffffffffu, s[e], off);
    if (lane == 0) {
#pragma unroll
        for (int e = 0; e < NE; e++) wsum[warp][e] = s[e];
    }
    __syncthreads();
    if (warp == 0) {
        float r[NE];
#pragma unroll
        for (int e = 0; e < NE; e++) r[e] = wsum[lane][e];
#pragma unroll
        for (int off = 16; off; off >>= 1)
#pragma unroll
            for (int e = 0; e < NE; e++) r[e] += __shfl_xor_sync(0xffffffffu, r[e], off);
        if (lane == 0 && aux_out != nullptr) {
            float aux = 0.0f;
            const float invT = 1.0f / (float)T_TOK;
#pragma unroll
            for (int e = 0; e < NE; e++)
                aux += ((float)total[e] * invT) * (r[e] * invT);
            *aux_out = (float)NE * aux;
        }
    }
}

// ---------------- HMMA gathered expert GEMM ----------------------
// block 128x128x32, 8 warps (4 M x 2 N), warp tile 32x64, 4-stage pipe.
#define GBM 128
#define GBN 128
#define GBK 32
#define NITER (DIM / GBK)          // 32
#define ATILE 8192                 // 128 rows x 32 fp16
#define BTILE 8192                 // 32 rows x 128 fp16
#define STAGE_BYTES (ATILE + BTILE)   // 16384
#define NSTAGE 4
#define SMEM_DATA0 1024
#define SMEM_GEMM (SMEM_DATA0 + NSTAGE * STAGE_BYTES)   // 66560

__device__ __forceinline__ uint32_t sw_a(int row, int kb) {
    return (uint32_t)(row * 64 + ((kb ^ ((row >> 1) & 3)) << 4));
}
__device__ __forceinline__ uint32_t sw_b(int k, int nc) {
    return (uint32_t)(k * 256 + ((((nc & 7) ^ (k & 7)) | (nc & 8)) << 4));
}

__global__ void __launch_bounds__(256, 2) moe_hmma_kernel(
        const float* __restrict__ bias, float* __restrict__ out) {
    int e    = blockIdx.z;
    int m    = g_m[e];
    int row0 = blockIdx.y * GBM;
    if (row0 >= m) return;
    int col0 = blockIdx.x * GBN;

    extern __shared__ char smem[];
    uint32_t sb = smem_u32(smem);
    int tid  = threadIdx.x;
    int wid  = tid >> 5;
    int lane = tid & 31;
    int warp_m = wid & 3;       // m offset *32
    int warp_n = wid >> 2;      // n offset *64

    int*   stok  = reinterpret_cast<int*>(smem);          // [128]
    float* sprob = reinterpret_cast<float*>(smem + 512);  // [128]

    if (tid < GBM) {
        int gr  = row0 + tid;
        int tok = (gr < m) ? g_tokens[e * CAP + gr] : 0;
        stok[tid]  = tok;
        sprob[tid] = (gr < m) ? g_topprob[tok] : 0.0f;
    }
    __syncthreads();

    const __half* wbase = g_wh + (size_t)e * DIM * DIM + col0;   // [k][n] slab

    int ar = tid >> 2, ak = tid & 3;
    uint32_t ad0 = sw_a(ar, ak);
    uint32_t ad1 = sw_a(ar + 64, ak);
    size_t a0row = (size_t)stok[ar] * DIM;
    size_t a1row = (size_t)stok[ar + 64] * DIM;
    int bk = tid >> 3, bn = tid & 7;
    uint32_t bd0 = sw_b(bk, bn);
    uint32_t bd1 = sw_b(bk, bn + 8);

#define ISSUE_STAGE(S, KC0)                                                   \
    do {                                                                      \
        uint32_t st = sb + SMEM_DATA0 + (uint32_t)(S) * STAGE_BYTES;          \
        cpasync16(st + ad0,         g_xh + a0row + (KC0) + ak * 8);           \
        cpasync16(st + ad1,         g_xh + a1row + (KC0) + ak * 8);           \
        const __half* wrow = wbase + (size_t)((KC0) + bk) * DIM;              \
        cpasync16(st + ATILE + bd0, wrow + bn * 8);                           \
        cpasync16(st + ATILE + bd1, wrow + bn * 8 + 64);                      \
        cp_commit();                                                          \
    } while (0)

    int q = lane >> 3, r = lane & 7;
    uint32_t a_off[2][2];
#pragma unroll
    for (int mt = 0; mt < 2; mt++)
#pragma unroll
        for (int ks = 0; ks < 2; ks++) {
            int mm = warp_m * 32 + mt * 16 + (q & 1) * 8 + r;
            int kb = ks * 2 + (q >> 1);
            a_off[mt][ks] = sw_a(mm, kb);
        }
    uint32_t b_off[4][2];
#pragma unroll
    for (int nt2 = 0; nt2 < 4; nt2++)
#pragma unroll
        for (int ks = 0; ks < 2; ks++) {
            int kk = ks * 16 + (q & 1) * 8 + r;
            int nc = warp_n * 8 + nt2 * 2 + (q >> 1);
            b_off[nt2][ks] = sw_b(kk, nc);
        }

    float acc[2][8][4];
#pragma unroll
    for (int mt = 0; mt < 2; mt++)
#pragma unroll
        for (int nt = 0; nt < 8; nt++)
#pragma unroll
            for (int j = 0; j < 4; j++) acc[mt][nt][j] = 0.0f;

    ISSUE_STAGE(0, 0);
    ISSUE_STAGE(1, GBK);
    ISSUE_STAGE(2, 2 * GBK);

    int stage = 0;
    for (int c = 0; c < NITER; c++) {
        cp_wait2();
        __syncthreads();
        if (c + 3 < NITER) {
            int s3 = stage + 3;
            if (s3 >= NSTAGE) s3 -= NSTAGE;
            ISSUE_STAGE(s3, (c + 3) * GBK);
        }

        uint32_t st = sb + SMEM_DATA0 + (uint32_t)stage * STAGE_BYTES;
#pragma unroll
        for (int ks = 0; ks < 2; ks++) {
            uint32_t ah[2][4];
#pragma unroll
            for (int mt = 0; mt < 2; mt++)
                LDSM4(ah[mt][0], ah[mt][1], ah[mt][2], ah[mt][3], st + a_off[mt][ks]);
#pragma unroll
            for (int nt2 = 0; nt2 < 4; nt2++) {
                uint32_t t0, t1, t2, t3;
                LDSM4T(t0, t1, t2, t3, st + ATILE + b_off[nt2][ks]);
#pragma unroll
                for (int mt = 0; mt < 2; mt++) {
                    MMA16816(acc[mt][nt2 * 2],     ah[mt], t0, t1);
                    MMA16816(acc[mt][nt2 * 2 + 1], ah[mt], t2, t3);
                }
            }
        }
        stage++;
        if (stage >= NSTAGE) stage -= NSTAGE;
    }

    int tq = lane >> 2;
    int tr = lane & 3;
    const float* be = bias + (size_t)e * DIM;
#pragma unroll
    for (int nt = 0; nt < 8; nt++) {
        int col = col0 + warp_n * 64 + nt * 8 + tr * 2;
        float2 bb = *reinterpret_cast<const float2*>(be + col);
#pragma unroll
        for (int mt = 0; mt < 2; mt++) {
#pragma unroll
            for (int h = 0; h < 2; h++) {
                int rw = warp_m * 32 + mt * 16 + h * 8 + tq;
                int gr = row0 + rw;
                if (gr < m) {
                    int   tok = stok[rw];
                    float p   = sprob[rw];
                    float2 o;
                    o.x = (acc[mt][nt][h * 2 + 0] + bb.x) * p;
                    o.y = (acc[mt][nt][h * 2 + 1] + bb.y) * p;
                    *reinterpret_cast<float2*>(out + (size_t)tok * DIM + col) = o;
                }
            }
        }
    }
}

// ---------------- launch ----------------
extern "C" void kernel_launch(void* const* d_in, const int* in_sizes, int n_in,
                              void* d_out, int out_size) {
    const float* x  = (const float*)d_in[0];   // [T, D]
    const float* Wg = (const float*)d_in[1];   // [D, E]
    const float* bg = (const float*)d_in[2];   // [E]
    const float* W  = (const float*)d_in[3];   // [E, D, D]
    const float* b  = (const float*)d_in[4];   // [E, D]
    float* out = (float*)d_out;

    // streaming: W fp16 convert + zero(out)  (low regs, high occupancy)
    wconv_zero_kernel<<<WZ_BLOCKS, 256>>>(W, out);

    // gating + x fp16 convert (2 tok/warp), alone on the GPU
    gating_kernel<<<256, 256>>>(x, Wg, bg);

    // routing scan + aux loss
    float* aux_out = (out_size > T_TOK * DIM) ? (out + (size_t)T_TOK * DIM) : nullptr;
    route_kernel<<<1, 1024>>>(aux_out);

    // HMMA gathered expert GEMM (single-pass fp16, trans-B)
    cudaFuncSetAttribute(moe_hmma_kernel,
                         cudaFuncAttributeMaxDynamicSharedMemorySize, SMEM_GEMM);
    dim3 grid(DIM / GBN, (CAP + GBM - 1) / GBM, NE);
    moe_hmma_kernel<<<grid, 256, SMEM_GEMM>>>(b, out);
}